// round 1
// baseline (speedup 1.0000x reference)
#include <cuda_runtime.h>

// NeighborList: all i<j pairs, minimum-image PBC wrap, cutoff mask.
// Output layout (float32, flattened in reference-return order):
//   [0,   P)    pair_i   (mask ? i : -1)
//   [P,  2P)    pair_j   (mask ? j : -1)
//   [2P, 5P)    deltas   [P,3] (mask ? wrapped delta : 0)
//   [5P, 6P)    distances (mask ? dist : 0)

__device__ float g_inv[9];
__device__ int   g_cell_zero;

__global__ void prep_kernel(const float* __restrict__ cell) {
    // single thread: compute inverse of safe_cell (= I if cell is all-zero)
    bool zero = true;
    float c[9];
#pragma unroll
    for (int k = 0; k < 9; k++) {
        c[k] = cell[k];
        if (c[k] != 0.0f) zero = false;
    }
    if (zero) {
        c[0] = c[4] = c[8] = 1.0f;
        c[1] = c[2] = c[3] = c[5] = c[6] = c[7] = 0.0f;
    }
    float a = c[0], b = c[1], cc = c[2];
    float d = c[3], e = c[4], f  = c[5];
    float g = c[6], h = c[7], i  = c[8];
    float A =  (e * i - f * h);
    float B = -(d * i - f * g);
    float C =  (d * h - e * g);
    float det = a * A + b * B + cc * C;
    float invdet = 1.0f / det;
    g_inv[0] = A * invdet;
    g_inv[1] = -(b * i - cc * h) * invdet;
    g_inv[2] =  (b * f - cc * e) * invdet;
    g_inv[3] = B * invdet;
    g_inv[4] =  (a * i - cc * g) * invdet;
    g_inv[5] = -(a * f - cc * d) * invdet;
    g_inv[6] = C * invdet;
    g_inv[7] = -(a * h - b * g) * invdet;
    g_inv[8] =  (a * e - b * d) * invdet;
    g_cell_zero = zero ? 1 : 0;
}

__global__ void nl_kernel(const float* __restrict__ xyz,
                          const float* __restrict__ cell,
                          float* __restrict__ out,
                          int n, size_t P) {
    const int i = blockIdx.y;
    const int j = blockIdx.x * blockDim.x + threadIdx.x;
    if (j >= n || j <= i) return;

    const float xi = __ldg(&xyz[3 * i + 0]);
    const float yi = __ldg(&xyz[3 * i + 1]);
    const float zi = __ldg(&xyz[3 * i + 2]);
    const float xj = __ldg(&xyz[3 * j + 0]);
    const float yj = __ldg(&xyz[3 * j + 1]);
    const float zj = __ldg(&xyz[3 * j + 2]);

    float dx = xi - xj;
    float dy = yi - yj;
    float dz = zi - zj;

    if (!g_cell_zero) {
        // frac = delta @ inv_cell  (row-vector x row-major matrix)
        const float f0 = dx * g_inv[0] + dy * g_inv[3] + dz * g_inv[6];
        const float f1 = dx * g_inv[1] + dy * g_inv[4] + dz * g_inv[7];
        const float f2 = dx * g_inv[2] + dy * g_inv[5] + dz * g_inv[8];
        // jnp.round = round-half-to-even = rintf
        const float r0 = rintf(f0);
        const float r1 = rintf(f1);
        const float r2 = rintf(f2);
        // wrapped = delta - round(frac) @ cell
        dx -= r0 * cell[0] + r1 * cell[3] + r2 * cell[6];
        dy -= r0 * cell[1] + r1 * cell[4] + r2 * cell[7];
        dz -= r0 * cell[2] + r1 * cell[5] + r2 * cell[8];
    }

    const float dist = sqrtf(dx * dx + dy * dy + dz * dz);
    const bool m = (dist <= 5.0f);

    // row-major upper-triangle linear index
    const size_t off = (size_t)i * (2 * (size_t)n - (size_t)i - 1) / 2;
    const size_t p = off + (size_t)(j - i - 1);

    out[p]     = m ? (float)i : -1.0f;
    out[P + p] = m ? (float)j : -1.0f;
    float* dptr = out + 2 * P + 3 * p;
    dptr[0] = m ? dx : 0.0f;
    dptr[1] = m ? dy : 0.0f;
    dptr[2] = m ? dz : 0.0f;
    out[5 * P + p] = m ? dist : 0.0f;
}

extern "C" void kernel_launch(void* const* d_in, const int* in_sizes, int n_in,
                              void* d_out, int out_size) {
    const float* xyz  = (const float*)d_in[0];
    const float* cell = (const float*)d_in[1];
    // defensive: metadata order is (xyz, cell); swap if sizes indicate otherwise
    if (n_in >= 2 && in_sizes[0] == 9 && in_sizes[1] != 9) {
        const float* t = xyz; xyz = cell; cell = t;
    }
    const int n = (in_sizes[0] == 9 && n_in >= 2) ? in_sizes[1] / 3 : in_sizes[0] / 3;
    const size_t P = (size_t)n * (size_t)(n - 1) / 2;

    prep_kernel<<<1, 1>>>(cell);

    const int TPB = 256;
    dim3 grid((n + TPB - 1) / TPB, n);
    nl_kernel<<<grid, TPB>>>(xyz, cell, (float*)d_out, n, P);
}

// round 2
// speedup vs baseline: 1.5207x; 1.5207x over previous
#include <cuda_runtime.h>

// NeighborList: all i<j pairs, minimum-image PBC, cutoff mask.
// Output (float32): [0,P) pair_i | [P,2P) pair_j | [2P,5P) deltas[P,3] | [5P,6P) dist

__device__ float g_inv[9];
__device__ float g_cell[9];
__device__ int   g_cell_zero;

__global__ void prep_kernel(const float* __restrict__ cell) {
    bool zero = true;
    float c[9];
#pragma unroll
    for (int k = 0; k < 9; k++) {
        c[k] = cell[k];
        if (c[k] != 0.0f) zero = false;
    }
    if (zero) {
        c[0] = c[4] = c[8] = 1.0f;
        c[1] = c[2] = c[3] = c[5] = c[6] = c[7] = 0.0f;
    }
#pragma unroll
    for (int k = 0; k < 9; k++) g_cell[k] = c[k];

    float a = c[0], b = c[1], cc = c[2];
    float d = c[3], e = c[4], f  = c[5];
    float g = c[6], h = c[7], i  = c[8];
    float A =  (e * i - f * h);
    float B = -(d * i - f * g);
    float C =  (d * h - e * g);
    float det = a * A + b * B + cc * C;
    float invdet = 1.0f / det;
    g_inv[0] = A * invdet;
    g_inv[1] = -(b * i - cc * h) * invdet;
    g_inv[2] =  (b * f - cc * e) * invdet;
    g_inv[3] = B * invdet;
    g_inv[4] =  (a * i - cc * g) * invdet;
    g_inv[5] = -(a * f - cc * d) * invdet;
    g_inv[6] = C * invdet;
    g_inv[7] =  (a * h - b * g) * (-invdet);
    g_inv[8] =  (a * e - b * d) * invdet;
    g_cell_zero = zero ? 1 : 0;
}

#define TPB 256

__device__ __forceinline__ unsigned tri_off(unsigned i, unsigned T) {
    return (i * (T - i)) >> 1;   // i*(2n-1-i)/2, fits uint32 for n=4096
}

__global__ void __launch_bounds__(TPB)
nl_kernel(const float* __restrict__ xyz,
          float* __restrict__ out,
          int n, unsigned P) {
    const unsigned tid = threadIdx.x;
    const unsigned p0  = blockIdx.x * TPB;
    const unsigned p   = p0 + tid;

    __shared__ float sdel[TPB * 3];

    const unsigned T = 2u * (unsigned)n - 1u;

    float vi = -1.0f, vj = -1.0f, vd = 0.0f;
    float ddx = 0.0f, ddy = 0.0f, ddz = 0.0f;

    if (p < P) {
        // ---- unrank p -> (i, j) on the strict upper triangle ----
        const unsigned D = T * T - 8u * p;          // >= 1, < 2^31
        const float s = sqrtf((float)D);
        int i = (int)(((float)T - s) * 0.5f);
        if (i < 0) i = 0;
        if (i > n - 2) i = n - 2;
        unsigned offi = tri_off((unsigned)i, T);
        while (offi > p) { i--; offi = tri_off((unsigned)i, T); }
        unsigned offn = tri_off((unsigned)(i + 1), T);
        while (offn <= p && i < n - 2) { i++; offi = offn; offn = tri_off((unsigned)(i + 1), T); }
        const int j = i + 1 + (int)(p - offi);

        // ---- delta + minimum image ----
        float dx = xyz[3 * i + 0] - xyz[3 * j + 0];
        float dy = xyz[3 * i + 1] - xyz[3 * j + 1];
        float dz = xyz[3 * i + 2] - xyz[3 * j + 2];

        if (!g_cell_zero) {
            const float f0 = dx * g_inv[0] + dy * g_inv[3] + dz * g_inv[6];
            const float f1 = dx * g_inv[1] + dy * g_inv[4] + dz * g_inv[7];
            const float f2 = dx * g_inv[2] + dy * g_inv[5] + dz * g_inv[8];
            const float r0 = rintf(f0);   // jnp.round = half-to-even
            const float r1 = rintf(f1);
            const float r2 = rintf(f2);
            dx -= r0 * g_cell[0] + r1 * g_cell[3] + r2 * g_cell[6];
            dy -= r0 * g_cell[1] + r1 * g_cell[4] + r2 * g_cell[7];
            dz -= r0 * g_cell[2] + r1 * g_cell[5] + r2 * g_cell[8];
        }

        const float dist = sqrtf(dx * dx + dy * dy + dz * dz);
        const bool m = (dist <= 5.0f);

        vi = m ? (float)i : -1.0f;
        vj = m ? (float)j : -1.0f;
        vd = m ? dist : 0.0f;
        ddx = m ? dx : 0.0f;
        ddy = m ? dy : 0.0f;
        ddz = m ? dz : 0.0f;

        // direct coalesced planes
        out[p]                   = vi;
        out[(size_t)P + p]       = vj;
        out[5 * (size_t)P + p]   = vd;
    }

    // ---- stage deltas in smem, flush as float4 (coalesced) ----
    sdel[3 * tid + 0] = ddx;
    sdel[3 * tid + 1] = ddy;
    sdel[3 * tid + 2] = ddz;
    __syncthreads();

    float* dbase = out + 2 * (size_t)P + (size_t)p0 * 3;
    const bool aligned16 = ((2 * (size_t)P) & 3u) == 0;  // byte offset 8P % 16 == 0
    if (aligned16 && (p0 + TPB <= P)) {
        if (tid < (TPB * 3) / 4) {
            reinterpret_cast<float4*>(dbase)[tid] =
                reinterpret_cast<const float4*>(sdel)[tid];
        }
    } else if (p0 < P) {
        const unsigned nvalid = (P - p0 < TPB) ? (P - p0) : TPB;
        for (unsigned k = tid; k < nvalid * 3; k += TPB) dbase[k] = sdel[k];
    }
}

extern "C" void kernel_launch(void* const* d_in, const int* in_sizes, int n_in,
                              void* d_out, int out_size) {
    const float* xyz  = (const float*)d_in[0];
    const float* cell = (const float*)d_in[1];
    if (n_in >= 2 && in_sizes[0] == 9 && in_sizes[1] != 9) {
        const float* t = xyz; xyz = cell; cell = t;
    }
    const int n = (in_sizes[0] == 9 && n_in >= 2) ? in_sizes[1] / 3 : in_sizes[0] / 3;
    const unsigned P = (unsigned)((size_t)n * (size_t)(n - 1) / 2);

    prep_kernel<<<1, 1>>>(cell);

    const unsigned blocks = (P + TPB - 1) / TPB;
    nl_kernel<<<blocks, TPB>>>(xyz, (float*)d_out, n, P);
}

// round 3
// speedup vs baseline: 1.7932x; 1.1792x over previous
#include <cuda_runtime.h>

// NeighborList: all i<j pairs, minimum-image PBC, cutoff mask.
// Output (float32): [0,P) pair_i | [P,2P) pair_j | [2P,5P) deltas[P,3] | [5P,6P) dist

#define MAXN 8192
#define TPB  256

__device__ float g_x[MAXN], g_y[MAXN], g_z[MAXN];
__device__ float g_inv[9];
__device__ float g_cellm[9];
__device__ int   g_cell_zero;

__global__ void prep_cell(const float* __restrict__ cell) {
    bool zero = true;
    float c[9];
#pragma unroll
    for (int k = 0; k < 9; k++) {
        c[k] = cell[k];
        if (c[k] != 0.0f) zero = false;
    }
    if (zero) {
        c[0] = c[4] = c[8] = 1.0f;
        c[1] = c[2] = c[3] = c[5] = c[6] = c[7] = 0.0f;
    }
#pragma unroll
    for (int k = 0; k < 9; k++) g_cellm[k] = c[k];

    float a = c[0], b = c[1], cc = c[2];
    float d = c[3], e = c[4], f  = c[5];
    float g = c[6], h = c[7], i  = c[8];
    float A =  (e * i - f * h);
    float B = -(d * i - f * g);
    float C =  (d * h - e * g);
    float det = a * A + b * B + cc * C;
    float invdet = 1.0f / det;
    g_inv[0] = A * invdet;
    g_inv[1] = -(b * i - cc * h) * invdet;
    g_inv[2] =  (b * f - cc * e) * invdet;
    g_inv[3] = B * invdet;
    g_inv[4] =  (a * i - cc * g) * invdet;
    g_inv[5] = -(a * f - cc * d) * invdet;
    g_inv[6] = C * invdet;
    g_inv[7] = -(a * h - b * g) * invdet;
    g_inv[8] =  (a * e - b * d) * invdet;
    g_cell_zero = zero ? 1 : 0;
}

__global__ void prep_soa(const float* __restrict__ xyz, int n) {
    int k = blockIdx.x * blockDim.x + threadIdx.x;
    if (k < n) {
        g_x[k] = xyz[3 * k + 0];
        g_y[k] = xyz[3 * k + 1];
        g_z[k] = xyz[3 * k + 2];
    }
}

__device__ __forceinline__ unsigned tri_off(unsigned i, unsigned T) {
    return (i * (T - i)) >> 1;   // i*(2n-1-i)/2
}

__global__ void __launch_bounds__(TPB)
nl_kernel(float* __restrict__ out, int n, unsigned P) {
    const unsigned t = blockIdx.x * TPB + threadIdx.x;
    const unsigned p = 4u * t;
    if (p >= P) return;

    const unsigned T = 2u * (unsigned)n - 1u;

    // ---- unrank p -> (i, j) ----
    const unsigned D = T * T - 8u * p;
    const float s = sqrtf((float)D);
    int i = (int)(((float)T - s) * 0.5f);
    if (i < 0) i = 0;
    if (i > n - 2) i = n - 2;
    unsigned offi = tri_off((unsigned)i, T);
    while (offi > p) { i--; offi = tri_off((unsigned)i, T); }
    unsigned rowend = tri_off((unsigned)(i + 1), T);
    while (rowend <= p && i < n - 2) {
        i++; offi = rowend; rowend = tri_off((unsigned)(i + 1), T);
    }
    int j = i + 1 + (int)(p - offi);

    // ---- hoist cell matrices into registers (once per 4 pairs) ----
    const int czero = g_cell_zero;
    float inv[9], cel[9];
    if (!czero) {
#pragma unroll
        for (int k = 0; k < 9; k++) { inv[k] = g_inv[k]; cel[k] = g_cellm[k]; }
    }

    float xi = g_x[i], yi = g_y[i], zi = g_z[i];

    float oi[4], oj[4], od[4], del[12];
    const unsigned nv = (P - p < 4u) ? (P - p) : 4u;

#pragma unroll
    for (int k = 0; k < 4; k++) {
        if ((unsigned)k >= nv) { oi[k] = oj[k] = od[k] = 0.0f;
                                 del[3*k] = del[3*k+1] = del[3*k+2] = 0.0f; continue; }
        if (p + (unsigned)k == rowend) {        // row crossing (rare)
            i++; j = i + 1;
            rowend = tri_off((unsigned)(i + 1), T);
            xi = g_x[i]; yi = g_y[i]; zi = g_z[i];
        }

        float dx = xi - g_x[j];
        float dy = yi - g_y[j];
        float dz = zi - g_z[j];

        if (!czero) {
            const float f0 = dx * inv[0] + dy * inv[3] + dz * inv[6];
            const float f1 = dx * inv[1] + dy * inv[4] + dz * inv[7];
            const float f2 = dx * inv[2] + dy * inv[5] + dz * inv[8];
            const float r0 = rintf(f0);   // jnp.round = half-to-even
            const float r1 = rintf(f1);
            const float r2 = rintf(f2);
            dx -= r0 * cel[0] + r1 * cel[3] + r2 * cel[6];
            dy -= r0 * cel[1] + r1 * cel[4] + r2 * cel[7];
            dz -= r0 * cel[2] + r1 * cel[5] + r2 * cel[8];
        }

        const float dist = sqrtf(dx * dx + dy * dy + dz * dz);
        const bool m = (dist <= 5.0f);

        oi[k] = m ? (float)i : -1.0f;
        oj[k] = m ? (float)j : -1.0f;
        od[k] = m ? dist : 0.0f;
        del[3*k + 0] = m ? dx : 0.0f;
        del[3*k + 1] = m ? dy : 0.0f;
        del[3*k + 2] = m ? dz : 0.0f;
        j++;
    }

    if (nv == 4u) {
        // all vector stores are 16B-aligned: P % 4 == 0, p % 4 == 0
        *reinterpret_cast<float4*>(out + p) =
            make_float4(oi[0], oi[1], oi[2], oi[3]);
        *reinterpret_cast<float4*>(out + (size_t)P + p) =
            make_float4(oj[0], oj[1], oj[2], oj[3]);
        *reinterpret_cast<float4*>(out + 5 * (size_t)P + p) =
            make_float4(od[0], od[1], od[2], od[3]);
        float* db = out + 2 * (size_t)P + 3 * (size_t)p;   // byte off 8P+48t, 16B-aligned
        *reinterpret_cast<float4*>(db + 0) = make_float4(del[0], del[1], del[2],  del[3]);
        *reinterpret_cast<float4*>(db + 4) = make_float4(del[4], del[5], del[6],  del[7]);
        *reinterpret_cast<float4*>(db + 8) = make_float4(del[8], del[9], del[10], del[11]);
    } else {
        for (unsigned k = 0; k < nv; k++) {
            out[p + k]                 = oi[k];
            out[(size_t)P + p + k]     = oj[k];
            out[5 * (size_t)P + p + k] = od[k];
            out[2 * (size_t)P + 3 * ((size_t)p + k) + 0] = del[3*k + 0];
            out[2 * (size_t)P + 3 * ((size_t)p + k) + 1] = del[3*k + 1];
            out[2 * (size_t)P + 3 * ((size_t)p + k) + 2] = del[3*k + 2];
        }
    }
}

extern "C" void kernel_launch(void* const* d_in, const int* in_sizes, int n_in,
                              void* d_out, int out_size) {
    const float* xyz  = (const float*)d_in[0];
    const float* cell = (const float*)d_in[1];
    if (n_in >= 2 && in_sizes[0] == 9 && in_sizes[1] != 9) {
        const float* t = xyz; xyz = cell; cell = t;
    }
    const int n = (in_sizes[0] == 9 && n_in >= 2) ? in_sizes[1] / 3 : in_sizes[0] / 3;
    const unsigned P = (unsigned)((size_t)n * (size_t)(n - 1) / 2);

    prep_cell<<<1, 1>>>(cell);
    prep_soa<<<(n + TPB - 1) / TPB, TPB>>>(xyz, n);

    const unsigned nthreads = (P + 3) / 4;
    const unsigned blocks = (nthreads + TPB - 1) / TPB;
    nl_kernel<<<blocks, TPB>>>((float*)d_out, n, P);
}